// round 12
// baseline (speedup 1.0000x reference)
#include <cuda_runtime.h>
#include <cuda_fp16.h>
#include <cstdint>

#define BB 512
#define NN 2048
#define QDIM 64
#define HH 8
#define KDIM 8
#define VDIM 8
#define ODIM 64

// device scratch (no allocations allowed)
__device__ float g_wavg[BB * HH * VDIM];     // [B][64]
__device__ __half g_w1h[QDIM * 64];          // gating_w transposed [n][k] fp16
__device__ __half g_w2h[QDIM * 64];          // output_w transposed [n][k] fp16

// ---------------------------------------------------------------------------
// helpers
// ---------------------------------------------------------------------------
__device__ __forceinline__ void ldsm_x4(uint32_t r[4], uint32_t saddr) {
    asm volatile("ldmatrix.sync.aligned.m8n8.x4.shared.b16 {%0,%1,%2,%3}, [%4];"
                 : "=r"(r[0]), "=r"(r[1]), "=r"(r[2]), "=r"(r[3]) : "r"(saddr));
}

__device__ __forceinline__ void mma_f16(float c[4], const uint32_t a[4],
                                        uint32_t b0, uint32_t b1) {
    asm volatile(
        "mma.sync.aligned.m16n8k16.row.col.f32.f16.f16.f32 "
        "{%0,%1,%2,%3}, {%4,%5,%6,%7}, {%8,%9}, {%0,%1,%2,%3};"
        : "+f"(c[0]), "+f"(c[1]), "+f"(c[2]), "+f"(c[3])
        : "r"(a[0]), "r"(a[1]), "r"(a[2]), "r"(a[3]), "r"(b0), "r"(b1));
}

__device__ __forceinline__ uint32_t pack_h2(float x, float y) {
    __half2 h = __floats2half2_rn(x, y);
    return *reinterpret_cast<uint32_t*>(&h);
}

// ---------------------------------------------------------------------------
// Kernel 12 (fused k1+k2): one block per batch, 256 threads (8 warps).
// Blocks 0-15 additionally do the one-time fp16 weight transpose (was k0).
// ---------------------------------------------------------------------------
#define BP 72                                 // B smem pitch (halves)
#define SM_B 0
#define SM_M 2304                             // B: 16*72*2 = 2304 B
#define TILEB (128 * BP * 2)                  // 18432 B per tile buffer
#define K12_SMEM (SM_M + 2 * TILEB)           // 39168 B dynamic

__global__ void __launch_bounds__(256) k12_attn(
    const float* __restrict__ q_data, const float* __restrict__ m_data,
    const float* __restrict__ q_mask, const float* __restrict__ query_w,
    const float* __restrict__ key_w, const float* __restrict__ value_w,
    const float* __restrict__ gating_w, const float* __restrict__ output_w)
{
    extern __shared__ __align__(16) char smraw[];
    __half* WB = (__half*)(smraw + SM_B);               // [16][BP]
    float* sc = (float*)(smraw + SM_M);                 // stage-A scratch

    __shared__ float qavg_s[64], qs_s[64], kw_s[512], smm[16];
    __shared__ float redA[8][4][8][2];
    __shared__ float redS[8][8];

    int b = blockIdx.x;
    int t = threadIdx.x;

    // ---- folded k0: blocks 0-15 convert/transpose gate weights ----
    if (b < 16) {
        int i = b * 256 + t;                  // i = k*64+n
        int k = i >> 6, n = i & 63;
        g_w1h[n * 64 + k] = __float2half_rn(gating_w[i]);
        g_w2h[n * 64 + k] = __float2half_rn(output_w[i]);
    }

    // ---------------- Stage A1: masked mean of q_data ----------------
    {
        int g = t >> 4, l = t & 15;
        const float4* qp = (const float4*)(q_data + (size_t)b * NN * QDIM);
        const float* mb = q_mask + (size_t)b * NN;
        float4 acc = make_float4(0.f, 0.f, 0.f, 0.f);
        float ms = 0.f;
        #pragma unroll 4
        for (int n = g; n < NN; n += 16) {
            float qm = mb[n];
            float4 qv = qp[(size_t)n * 16 + l];
            acc.x += qm * qv.x; acc.y += qm * qv.y;
            acc.z += qm * qv.z; acc.w += qm * qv.w;
            ms += qm;
        }
        *(float4*)&sc[g * 64 + l * 4] = acc;
        if (l == 0) smm[g] = ms;
        __syncthreads();
        if (t < 64) {
            float tot = 0.f, mt = 0.f;
            #pragma unroll
            for (int gg = 0; gg < 16; ++gg) { tot += sc[gg * 64 + t]; mt += smm[gg]; }
            qavg_s[t] = tot / (mt + 1e-10f);
        }
    }
    for (int i = t; i < 512; i += 256) kw_s[i] = key_w[i];
    __syncthreads();

    // ---------------- Stage A2: q = (qavg @ query_w)*scale ----------------
    {
        int col = t & 63, seg = t >> 6;
        float v = 0.f;
        #pragma unroll
        for (int a = seg * 16; a < seg * 16 + 16; ++a)
            v += qavg_s[a] * query_w[a * 64 + col];
        sc[seg * 64 + col] = v;
    }
    __syncthreads();
    if (t < 64)
        qs_s[t] = (sc[t] + sc[64 + t] + sc[128 + t] + sc[192 + t]) * 0.3535533905932738f;
    __syncthreads();

    // ---------------- Stage A3: build B = [P^T ; value_w^T] fp16 ----------------
    for (int i = t; i < 512; i += 256) {
        int a = i >> 3, h = i & 7;
        float p = 0.f;
        #pragma unroll
        for (int kd = 0; kd < 8; ++kd) p += kw_s[a * 8 + kd] * qs_s[h * 8 + kd];
        WB[h * BP + a] = __float2half_rn(p);
    }
    for (int i = t; i < 512; i += 256) {
        int a = i >> 3, c = i & 7;
        WB[(8 + c) * BP + a] = __float2half_rn(value_w[a * 8 + c]);
    }
    __syncthreads();

    // ---------------- fragment geometry ----------------
    uint32_t sbase = (uint32_t)__cvta_generic_to_shared(smraw);
    int w = t >> 5, lane = t & 31;
    int gid = lane >> 2;
    int l7 = lane & 7;
    int a_r  = l7 + ((lane >> 3) & 1) * 8;
    int a_kh = (lane >> 4) * 8;
    int b_n  = ((lane >> 4) << 3) + l7;
    int b_kh = ((lane >> 3) & 1) * 8;

    uint32_t bf[4][4];
    #pragma unroll
    for (int k0 = 0; k0 < 4; ++k0) {
        uint32_t bd = sbase + (uint32_t)(SM_B) + (uint32_t)(b_n * BP + k0 * 16 + b_kh) * 2u;
        ldsm_x4(bf[k0], bd);
    }

    const float4* mp4 = (const float4*)(m_data + (size_t)b * NN * QDIM);
    const float* qmp = q_mask + (size_t)b * NN;

    float acc[8][2], S[8];
    #pragma unroll
    for (int h = 0; h < 8; ++h) { acc[h][0] = 0.f; acc[h][1] = 0.f; S[h] = 0.f; }

    // prologue: load tile 0 into buffer 0
    {
        float4 st[8];
        #pragma unroll
        for (int s = 0; s < 8; ++s) st[s] = mp4[t + 256 * s];
        __half* Mb = (__half*)(smraw + SM_M);
        #pragma unroll
        for (int s = 0; s < 8; ++s) {
            int j = t + 256 * s;
            int row = j >> 4, c4 = j & 15;
            __half2* dst = (__half2*)(Mb + row * BP + c4 * 4);
            dst[0] = __floats2half2_rn(st[s].x, st[s].y);
            dst[1] = __floats2half2_rn(st[s].z, st[s].w);
        }
    }
    __syncthreads();

    // ---------------- main loop: 16 tiles of 128 rows ----------------
    for (int it = 0; it < 16; ++it) {
        int buf = it & 1;
        int rbase = it * 128;

        float4 st[8];
        if (it < 15) {
            const float4* src = mp4 + (size_t)(rbase + 128) * 16;
            #pragma unroll
            for (int s = 0; s < 8; ++s) st[s] = src[t + 256 * s];
        }

        float c0[4] = {0.f, 0.f, 0.f, 0.f};
        float c1[4] = {0.f, 0.f, 0.f, 0.f};
        uint32_t mb_ad = sbase + (uint32_t)(SM_M + buf * TILEB) +
                         (uint32_t)((w * 16 + a_r) * BP + a_kh) * 2u;
        #pragma unroll
        for (int k0 = 0; k0 < 4; ++k0) {
            uint32_t am[4];
            ldsm_x4(am, mb_ad + k0 * 32u);
            mma_f16(c0, am, bf[k0][0], bf[k0][1]);   // logits
            mma_f16(c1, am, bf[k0][2], bf[k0][3]);   // v
        }

        float mA = qmp[rbase + w * 16 + gid];
        float mB = qmp[rbase + w * 16 + gid + 8];
        float wA0 = mA * __expf(c0[0]);
        float wA1 = mA * __expf(c0[1]);
        float wB0 = mB * __expf(c0[2]);
        float wB1 = mB * __expf(c0[3]);

        int qb = lane & ~3;
        #pragma unroll
        for (int src = 0; src < 4; ++src) {
            float hA0 = __shfl_sync(0xffffffffu, wA0, qb + src);
            float hA1 = __shfl_sync(0xffffffffu, wA1, qb + src);
            float hB0 = __shfl_sync(0xffffffffu, wB0, qb + src);
            float hB1 = __shfl_sync(0xffffffffu, wB1, qb + src);
            int h0 = 2 * src, h1 = 2 * src + 1;
            acc[h0][0] += hA0 * c1[0]; acc[h0][1] += hA0 * c1[1];
            acc[h1][0] += hA1 * c1[0]; acc[h1][1] += hA1 * c1[1];
            acc[h0][0] += hB0 * c1[2]; acc[h0][1] += hB0 * c1[3];
            acc[h1][0] += hB1 * c1[2]; acc[h1][1] += hB1 * c1[3];
            S[h0] += hA0 + hB0;
            S[h1] += hA1 + hB1;
        }

        if (it < 15) {
            __half* Mb = (__half*)(smraw + SM_M + (buf ^ 1) * TILEB);
            #pragma unroll
            for (int s = 0; s < 8; ++s) {
                int j = t + 256 * s;
                int row = j >> 4, c4 = j & 15;
                __half2* dst = (__half2*)(Mb + row * BP + c4 * 4);
                dst[0] = __floats2half2_rn(st[s].x, st[s].y);
                dst[1] = __floats2half2_rn(st[s].z, st[s].w);
            }
        }
        __syncthreads();
    }

    // ---------------- reduction ----------------
    #pragma unroll
    for (int off = 4; off <= 16; off <<= 1) {
        #pragma unroll
        for (int h = 0; h < 8; ++h) {
            acc[h][0] += __shfl_xor_sync(0xffffffffu, acc[h][0], off);
            acc[h][1] += __shfl_xor_sync(0xffffffffu, acc[h][1], off);
            S[h] += __shfl_xor_sync(0xffffffffu, S[h], off);
        }
    }
    if (lane < 4) {
        #pragma unroll
        for (int h = 0; h < 8; ++h) {
            redA[w][lane][h][0] = acc[h][0];
            redA[w][lane][h][1] = acc[h][1];
        }
        if (lane == 0) {
            #pragma unroll
            for (int h = 0; h < 8; ++h) redS[w][h] = S[h];
        }
    }
    __syncthreads();
    if (t < 64) {
        int h = t >> 3, c = t & 7;
        float a = 0.f, s = 0.f;
        #pragma unroll
        for (int w2 = 0; w2 < 8; ++w2) {
            a += redA[w2][c >> 1][h][c & 1];
            s += redS[w2][h];
        }
        g_wavg[b * 64 + h * 8 + c] = a / s;
    }
}

// ---------------------------------------------------------------------------
// Kernel 3: fp16 mma gate path, register-resident gate (no smem round-trip).
// TILE_T=128, 8 warps; warp w owns rows [16w,16w+16), full n=64.
// GEMM1 C-fragments -> sigmoid -> repacked directly as GEMM2 A-fragments.
// W2 is pre-scaled by wavg[b] (diag fold) during the smem fill.
// Exactly ONE __syncthreads in the kernel.
// ---------------------------------------------------------------------------
#define TILE_T 128
#define WPH 72
#define SM_W1H 0
#define SM_W2H 4608
#define SM_AH  9216
#define K3_SMEM_BYTES ((9216 + TILE_T * WPH) * 2)   // 36864 B

__global__ void __launch_bounds__(256) k3_gate(
    const float* __restrict__ q_data,
    const float* __restrict__ gating_b,
    const float* __restrict__ output_b,
    float* __restrict__ out)
{
    extern __shared__ __align__(16) __half smem_h[];
    __half* W1 = smem_h + SM_W1H;       // [64n][WPH]
    __half* W2 = smem_h + SM_W2H;       // [64n][WPH], scaled by wavg[k]
    __half* A  = smem_h + SM_AH;        // [128][WPH]
    __shared__ float b1s[64], b2s[64];

    int t = threadIdx.x;
    size_t tok0 = (size_t)blockIdx.x * TILE_T;
    int b = (int)(tok0 >> 11);

    // ---- hoist q-tile LDGs (DRAM) so they overlap weight fills (L2) ----
    const float4* qp = (const float4*)(q_data + tok0 * QDIM);
    float4 qv[8];
    #pragma unroll
    for (int s = 0; s < 8; ++s) qv[s] = qp[t + 256 * s];

    // ---- weights: W1 copy; W2 scaled by wavg[b][k] ----
    {
        const uint32_t* s1 = (const uint32_t*)g_w1h;
        const __half2* s2 = (const __half2*)g_w2h;
        uint32_t* d1 = (uint32_t*)W1;
        __half2* d2 = (__half2*)W2;
        const float* wvp = g_wavg + b * 64;
        #pragma unroll
        for (int j = t; j < 2048; j += 256) {
            int n = j >> 5, kp = j & 31;
            d1[n * (WPH / 2) + kp] = s1[j];
            __half2 hv = s2[j];
            float lo = __low2float(hv) * wvp[2 * kp];
            float hi = __high2float(hv) * wvp[2 * kp + 1];
            d2[n * (WPH / 2) + kp] = __floats2half2_rn(lo, hi);
        }
    }
    if (t < 64) {
        b1s[t] = gating_b[t];
        b2s[t] = output_b[t];
    }
    // ---- q tile -> fp16 smem ----
    #pragma unroll
    for (int s = 0; s < 8; ++s) {
        int i = t + 256 * s;
        int row = i >> 4;
        int k = (i & 15) << 2;
        *(half2*)&A[row * WPH + k]     = __floats2half2_rn(qv[s].x, qv[s].y);
        *(half2*)&A[row * WPH + k + 2] = __floats2half2_rn(qv[s].z, qv[s].w);
    }
    __syncthreads();   // the only barrier

    uint32_t sbase = (uint32_t)__cvta_generic_to_shared(smem_h);
    int w = t >> 5, lane = t & 31;
    int gid = lane >> 2, tid4 = lane & 3;
    int row0 = w * 16;

    int l7 = lane & 7;
    int a_r  = l7 + ((lane >> 3) & 1) * 8;
    int a_kh = (lane >> 4) * 8;
    int b_n  = ((lane >> 4) << 3) + l7;
    int b_kh = ((lane >> 3) & 1) * 8;

    // ================= GEMM1: C1 = A @ W1^T  (m16 x n64 per warp) =========
    float c1[8][4];
    #pragma unroll
    for (int nt = 0; nt < 8; ++nt)
        #pragma unroll
        for (int j = 0; j < 4; ++j) c1[nt][j] = 0.f;

    uint32_t a_ad = sbase + (uint32_t)(SM_AH + (row0 + a_r) * WPH + a_kh) * 2u;
    #pragma unroll
    for (int k0 = 0; k0 < 4; ++k0) {
        uint32_t am[4];
        ldsm_x4(am, a_ad + k0 * 32u);
        #pragma unroll
        for (int np = 0; np < 4; ++np) {
            uint32_t bb[4];
            uint32_t bd = sbase + (uint32_t)(SM_W1H +
                (np * 16 + b_n) * WPH + k0 * 16 + b_kh) * 2u;
            ldsm_x4(bb, bd);
            mma_f16(c1[2 * np],     am, bb[0], bb[1]);
            mma_f16(c1[2 * np + 1], am, bb[2], bb[3]);
        }
    }

    // ---- sigmoid in registers, repack as GEMM2 A-fragments ----
    uint32_t ga[4][4];
    #pragma unroll
    for (int nt = 0; nt < 8; ++nt) {
        int col = nt * 8 + 2 * tid4;
        float bl0 = b1s[col], bl1 = b1s[col + 1];
        float g0 = 1.f / (1.f + __expf(-(c1[nt][0] + bl0)));
        float g1 = 1.f / (1.f + __expf(-(c1[nt][1] + bl1)));
        float g2 = 1.f / (1.f + __expf(-(c1[nt][2] + bl0)));
        float g3 = 1.f / (1.f + __expf(-(c1[nt][3] + bl1)));
        int k0 = nt >> 1;          // k-chunk
        int half = nt & 1;         // 0: k-lo (a0,a1) ; 1: k-hi (a2,a3)
        ga[k0][2 * half]     = pack_h2(g0, g1);
        ga[k0][2 * half + 1] = pack_h2(g2, g3);
    }

    // ================= GEMM2: C2 = G @ W2'^T ==============================
    float c2[8][4];
    #pragma unroll
    for (int nt = 0; nt < 8; ++nt)
        #pragma unroll
        for (int j = 0; j < 4; ++j) c2[nt][j] = 0.f;

    #pragma unroll
    for (int k0 = 0; k0 < 4; ++k0) {
        #pragma unroll
        for (int np = 0; np < 4; ++np) {
            uint32_t bb[4];
            uint32_t bd = sbase + (uint32_t)(SM_W2H +
                (np * 16 + b_n) * WPH + k0 * 16 + b_kh) * 2u;
            ldsm_x4(bb, bd);
            mma_f16(c2[2 * np],     ga[k0], bb[0], bb[1]);
            mma_f16(c2[2 * np + 1], ga[k0], bb[2], bb[3]);
        }
    }

    // ---- epilogue: +bias, direct float2 stores ----
    float* op = out + tok0 * ODIM;
    #pragma unroll
    for (int nt = 0; nt < 8; ++nt) {
        int col = nt * 8 + 2 * tid4;
        float bl0 = b2s[col], bl1 = b2s[col + 1];
        int r0 = row0 + gid, r1 = r0 + 8;
        float2 o0, o1;
        o0.x = c2[nt][0] + bl0; o0.y = c2[nt][1] + bl1;
        o1.x = c2[nt][2] + bl0; o1.y = c2[nt][3] + bl1;
        *(float2*)&op[(size_t)r0 * ODIM + col] = o0;
        *(float2*)&op[(size_t)r1 * ODIM + col] = o1;
    }
}

// ---------------------------------------------------------------------------
extern "C" void kernel_launch(void* const* d_in, const int* in_sizes, int n_in,
                              void* d_out, int out_size) {
    (void)in_sizes; (void)n_in; (void)out_size;
    const float* q_data   = (const float*)d_in[0];
    const float* m_data   = (const float*)d_in[1];
    const float* q_mask   = (const float*)d_in[2];
    // d_in[3] = bias (dummy)
    const float* query_w  = (const float*)d_in[4];
    const float* key_w    = (const float*)d_in[5];
    const float* value_w  = (const float*)d_in[6];
    const float* gating_w = (const float*)d_in[7];
    const float* gating_b = (const float*)d_in[8];
    const float* output_w = (const float*)d_in[9];
    const float* output_b = (const float*)d_in[10];
    float* out = (float*)d_out;

    cudaFuncSetAttribute(k12_attn, cudaFuncAttributeMaxDynamicSharedMemorySize,
                         K12_SMEM);
    cudaFuncSetAttribute(k3_gate, cudaFuncAttributeMaxDynamicSharedMemorySize,
                         K3_SMEM_BYTES);

    k12_attn<<<BB, 256, K12_SMEM>>>(q_data, m_data, q_mask, query_w, key_w,
                                    value_w, gating_w, output_w);
    k3_gate<<<(BB * NN) / TILE_T, 256, K3_SMEM_BYTES>>>(q_data, gating_b,
                                                        output_b, out);
}